// round 16
// baseline (speedup 1.0000x reference)
#include <cuda_runtime.h>
#include <cstdint>
#include <math.h>

#define D 256
#define MAXN 8192
#define TILE 128
#define CHKB 144                     // smem row bytes: 144 = 9*16 (cp.async-aligned);
                                     // 36 words == 4 mod 32 -> conflict-free ldmatrix
#define ST_BYTES (TILE * CHKB)       // one stage = 18432 B (K-chunk of 128 s8)

// Scratch (__device__ globals: allocation-free rule)
__device__ int8_t g_znq[MAXN * D];   // normalized rows, s8 (scale 127), 2 MB
__device__ float g_S[MAXN];          // sum_{j!=i} exp(sim_ij - 2)
__device__ float g_pos[MAXN];        // sim[i, partner(i)]
__device__ unsigned int g_done;      // finished-CTA ticket (reset by last CTA)

__device__ __forceinline__ uint32_t smem_u32(const void* p) {
    uint32_t a;
    asm("{ .reg .u64 t; cvta.to.shared.u64 t, %1; cvt.u32.u64 %0, t; }"
        : "=r"(a) : "l"(p));
    return a;
}
__device__ __forceinline__ void cp_async16(uint32_t dst, const void* src) {
    asm volatile("cp.async.cg.shared.global [%0], [%1], 16;" :: "r"(dst), "l"(src));
}
#define CP_COMMIT() asm volatile("cp.async.commit_group;" ::: "memory")
#define CP_WAIT(n)  asm volatile("cp.async.wait_group %0;" :: "n"(n) : "memory")

// ---------------------------------------------------------------------------
// exp(sim-2) from the s32 accumulator via the MUFU pipe:
//   exp(sim-2) = 2^(a*C1 + C0);  1 cvt + 1 FMA + 1 ex2.approx per element.
// ---------------------------------------------------------------------------
#define EXP_C1 (1.7886898e-4f)        // 2 * log2(e) / 16129
#define EXP_C0 (-2.8853900817779268f) // -2 * log2(e)
__device__ __forceinline__ float exp2_mufu(float t) {
    float r;
    asm("ex2.approx.f32 %0, %1;" : "=f"(r) : "f"(t));
    return r;
}
__device__ __forceinline__ float lg2_mufu(float x) {
    float r;
    asm("lg2.approx.f32 %0, %1;" : "=f"(r) : "f"(x));
    return r;
}

// ---------------------------------------------------------------------------
// Kernel 1: normalize rows -> s8 (scale 127). Warp handles 2 rows (MLP x2,
// the kernel is latency-bound); 16 rows/block, grid 512.
// ---------------------------------------------------------------------------
__global__ __launch_bounds__(256)
void k_normalize(const float* __restrict__ zi,
                 const float* __restrict__ zj, int B) {
    const int w   = threadIdx.x >> 5;
    const int lid = threadIdx.x & 31;
    const int row0 = blockIdx.x * 16 + w * 2;

    const float* srcA = (row0 < B) ? (zi + (size_t)row0 * D)
                                   : (zj + (size_t)(row0 - B) * D);
    const int row1 = row0 + 1;
    const float* srcB = (row1 < B) ? (zi + (size_t)row1 * D)
                                   : (zj + (size_t)(row1 - B) * D);

    float4 a0 = *reinterpret_cast<const float4*>(srcA + lid * 8);
    float4 a1 = *reinterpret_cast<const float4*>(srcA + lid * 8 + 4);
    float4 b0 = *reinterpret_cast<const float4*>(srcB + lid * 8);
    float4 b1 = *reinterpret_cast<const float4*>(srcB + lid * 8 + 4);

    float sa = a0.x*a0.x + a0.y*a0.y + a0.z*a0.z + a0.w*a0.w
             + a1.x*a1.x + a1.y*a1.y + a1.z*a1.z + a1.w*a1.w;
    float sb = b0.x*b0.x + b0.y*b0.y + b0.z*b0.z + b0.w*b0.w
             + b1.x*b1.x + b1.y*b1.y + b1.z*b1.z + b1.w*b1.w;
    #pragma unroll
    for (int o = 16; o > 0; o >>= 1) {
        sa += __shfl_xor_sync(0xffffffffu, sa, o);
        sb += __shfl_xor_sync(0xffffffffu, sb, o);
    }
    float qa = 127.0f / fmaxf(sqrtf(sa), 1e-8f);
    float qb = 127.0f / fmaxf(sqrtf(sb), 1e-8f);

    auto pack8 = [](float4 v0, float4 v1, float q, uint2& pk) {
        int i0 = __float2int_rn(v0.x * q), i1 = __float2int_rn(v0.y * q);
        int i2 = __float2int_rn(v0.z * q), i3 = __float2int_rn(v0.w * q);
        int i4 = __float2int_rn(v1.x * q), i5 = __float2int_rn(v1.y * q);
        int i6 = __float2int_rn(v1.z * q), i7 = __float2int_rn(v1.w * q);
        pk.x = (uint32_t)(i0 & 255) | ((uint32_t)(i1 & 255) << 8) |
               ((uint32_t)(i2 & 255) << 16) | ((uint32_t)(i3 & 255) << 24);
        pk.y = (uint32_t)(i4 & 255) | ((uint32_t)(i5 & 255) << 8) |
               ((uint32_t)(i6 & 255) << 16) | ((uint32_t)(i7 & 255) << 24);
    };
    uint2 pa, pb;
    pack8(a0, a1, qa, pa);
    pack8(b0, b1, qb, pb);
    *reinterpret_cast<uint2*>(&g_znq[(size_t)row0 * D + lid * 8]) = pa;
    *reinterpret_cast<uint2*>(&g_znq[(size_t)row1 * D + lid * 8]) = pb;
    if (lid == 0) {
        g_S[row0] = 0.0f; g_pos[row0] = 0.0f;
        g_S[row1] = 0.0f; g_pos[row1] = 0.0f;
    }
}

// ---------------------------------------------------------------------------
// Kernel 2: lower-triangle 128x128 tiles (2080 CTAs), s8 mma.sync.m16n8k32,
// MUFU exp epilogue (identical mainloop/epilogue to R15). NEW: the final
// loss reduction is fused via a last-CTA ticket, removing the 3rd kernel.
// ---------------------------------------------------------------------------
__global__ __launch_bounds__(256, 2)
void k_simgemm_sym(int Nn, int B, int NT, float* __restrict__ out) {
    extern __shared__ uint8_t smem[];
    uint8_t* As = smem;                      // 2 stages
    uint8_t* Bs = smem + 2 * ST_BYTES;       // 2 stages

    // decode lower-triangle tile (by >= bx)
    int idx = blockIdx.x;
    int by = (int)((sqrtf(8.0f * (float)idx + 1.0f) - 1.0f) * 0.5f);
    while ((by + 1) * (by + 2) / 2 <= idx) by++;
    while (by * (by + 1) / 2 > idx) by--;
    int bx = idx - by * (by + 1) / 2;
    const int r0 = by * TILE, c0 = bx * TILE;
    const bool diag = (by == bx);

    const int tid = threadIdx.x;
    const int wid = tid >> 5, lid = tid & 31;

    auto issue_chunk = [&](int ch) {
        #pragma unroll
        for (int q = 0; q < 4; q++) {
            int li  = tid + q * 256;            // 0..1023
            int row = li >> 3;                  // 0..127
            int seg = (li & 7) << 4;            // 0..112 bytes
            uint32_t dstA = smem_u32(&As[ch * ST_BYTES + row * CHKB + seg]);
            uint32_t dstB = smem_u32(&Bs[ch * ST_BYTES + row * CHKB + seg]);
            cp_async16(dstA, &g_znq[(size_t)(r0 + row) * D + ch * 128 + seg]);
            cp_async16(dstB, &g_znq[(size_t)(c0 + row) * D + ch * 128 + seg]);
        }
        CP_COMMIT();
    };

    issue_chunk(0);
    issue_chunk(1);

    const int warp_m = wid & 3;
    const int warp_n = wid >> 2;

    uint32_t aAddr[2];
    #pragma unroll
    for (int mf = 0; mf < 2; mf++) {
        int row  = warp_m * 32 + mf * 16 + (lid & 15);
        int colb = (lid >> 4) << 4;
        aAddr[mf] = smem_u32(&As[row * CHKB + colb]);
    }
    uint32_t bAddr[4];
    #pragma unroll
    for (int nq = 0; nq < 4; nq++) {
        int row  = warp_n * 64 + nq * 16 + ((lid >> 4) << 3) + (lid & 7);
        int colb = (lid & 8) << 1;
        bAddr[nq] = smem_u32(&Bs[row * CHKB + colb]);
    }

    int acc[2][8][4];
    #pragma unroll
    for (int i = 0; i < 2; i++)
        #pragma unroll
        for (int j = 0; j < 8; j++)
            #pragma unroll
            for (int e = 0; e < 4; e++) acc[i][j][e] = 0;

    #pragma unroll
    for (int ch = 0; ch < 2; ch++) {
        if (ch == 0) CP_WAIT(1); else CP_WAIT(0);
        __syncthreads();
        const uint32_t cb = (uint32_t)ch * ST_BYTES;
        #pragma unroll
        for (int ks = 0; ks < 4; ks++) {
            const uint32_t kb = cb + ks * 32;
            uint32_t a[2][4], b[4][4];
            #pragma unroll
            for (int mf = 0; mf < 2; mf++)
                asm volatile("ldmatrix.sync.aligned.m8n8.x4.shared.b16 {%0,%1,%2,%3}, [%4];"
                             : "=r"(a[mf][0]), "=r"(a[mf][1]), "=r"(a[mf][2]), "=r"(a[mf][3])
                             : "r"(aAddr[mf] + kb));
            #pragma unroll
            for (int nq = 0; nq < 4; nq++)
                asm volatile("ldmatrix.sync.aligned.m8n8.x4.shared.b16 {%0,%1,%2,%3}, [%4];"
                             : "=r"(b[nq][0]), "=r"(b[nq][1]), "=r"(b[nq][2]), "=r"(b[nq][3])
                             : "r"(bAddr[nq] + kb));
            #pragma unroll
            for (int mf = 0; mf < 2; mf++)
                #pragma unroll
                for (int nf = 0; nf < 8; nf++) {
                    const int nq = nf >> 1, base = (nf & 1) * 2;
                    asm volatile(
                        "mma.sync.aligned.m16n8k32.row.col.s32.s8.s8.s32 "
                        "{%0,%1,%2,%3}, {%4,%5,%6,%7}, {%8,%9}, {%0,%1,%2,%3};"
                        : "+r"(acc[mf][nf][0]), "+r"(acc[mf][nf][1]),
                          "+r"(acc[mf][nf][2]), "+r"(acc[mf][nf][3])
                        : "r"(a[mf][0]), "r"(a[mf][1]), "r"(a[mf][2]), "r"(a[mf][3]),
                          "r"(b[nq][base]), "r"(b[nq][base + 1]));
                }
        }
    }

    // -------------------- epilogue (identical to R15) ----------------------
    const float SC = 2.0f / 16129.0f;
    const int qrow = lid >> 2, qcol = lid & 3;
    const bool has_pos = (by == bx + (B / TILE));
    float rs[4] = {0.f, 0.f, 0.f, 0.f};
    float cs[8][2];
    #pragma unroll
    for (int nf = 0; nf < 8; nf++) { cs[nf][0] = 0.f; cs[nf][1] = 0.f; }

    #pragma unroll
    for (int mf = 0; mf < 2; mf++) {
        #pragma unroll
        for (int sub = 0; sub < 2; sub++) {
            const int r = r0 + warp_m * 32 + mf * 16 + sub * 8 + qrow;
            const int partner = (r < B) ? (r + B) : (r - B);
            #pragma unroll
            for (int nf = 0; nf < 8; nf++) {
                #pragma unroll
                for (int e = 0; e < 2; e++) {
                    const int c = c0 + warp_n * 64 + nf * 8 + qcol * 2 + e;
                    const int av = acc[mf][nf][sub * 2 + e];
                    float ex = exp2_mufu(fmaf((float)av, EXP_C1, EXP_C0));
                    if (diag && c == r) ex = 0.0f;
                    rs[mf * 2 + sub] += ex;
                    if (!diag) cs[nf][e] += ex;
                    if (has_pos && c == partner) {
                        const float sim = SC * (float)av;
                        g_pos[r] = sim; g_pos[c] = sim;
                    }
                }
            }
        }
    }

    #pragma unroll
    for (int i = 0; i < 4; i++) {
        rs[i] += __shfl_xor_sync(0xffffffffu, rs[i], 1);
        rs[i] += __shfl_xor_sync(0xffffffffu, rs[i], 2);
    }
    if (qcol == 0) {
        #pragma unroll
        for (int mf = 0; mf < 2; mf++)
            #pragma unroll
            for (int sub = 0; sub < 2; sub++) {
                const int r = r0 + warp_m * 32 + mf * 16 + sub * 8 + qrow;
                atomicAdd(&g_S[r], rs[mf * 2 + sub]);
            }
    }
    if (!diag) {
        #pragma unroll
        for (int nf = 0; nf < 8; nf++) {
            #pragma unroll
            for (int e = 0; e < 2; e++) {
                float v = cs[nf][e];
                v += __shfl_xor_sync(0xffffffffu, v, 4);
                v += __shfl_xor_sync(0xffffffffu, v, 8);
                v += __shfl_xor_sync(0xffffffffu, v, 16);
                if (lid < 4) {
                    const int c = c0 + warp_n * 64 + nf * 8 + qcol * 2 + e;
                    atomicAdd(&g_S[c], v);
                }
            }
        }
    }

    // ---------------- fused final reduction (last-CTA ticket) --------------
    __shared__ unsigned int s_ticket;
    __threadfence();
    __syncthreads();
    if (tid == 0) s_ticket = atomicAdd(&g_done, 1u);
    __syncthreads();
    if (s_ticket == (unsigned int)(NT - 1)) {
        // all other CTAs' atomics/stores are visible (fence + atomic chain)
        const float LN2 = 0.6931471805599453f;
        float s = 0.0f;
        for (int i = tid; i < Nn; i += 256)
            s += fmaf(LN2, lg2_mufu(g_S[i]), 2.0f - g_pos[i]);
        #pragma unroll
        for (int o = 16; o > 0; o >>= 1) s += __shfl_xor_sync(0xffffffffu, s, o);
        __shared__ float ws[8];
        if (lid == 0) ws[wid] = s;
        __syncthreads();
        if (tid < 32) {
            float x = (tid < 8) ? ws[tid] : 0.0f;
            #pragma unroll
            for (int o = 4; o > 0; o >>= 1) x += __shfl_xor_sync(0xffffffffu, x, o);
            if (tid == 0) {
                out[0] = x / (float)Nn;
                g_done = 0;     // reset for next graph replay (deterministic)
            }
        }
    }
}

// ---------------------------------------------------------------------------
extern "C" void kernel_launch(void* const* d_in, const int* in_sizes, int n_in,
                              void* d_out, int out_size) {
    const float* zi = (const float*)d_in[0];
    const float* zj = (const float*)d_in[1];
    int B  = in_sizes[0] / D;   // 4096
    int Nn = 2 * B;             // 8192

    const int smem_bytes = 4 * ST_BYTES;   // 73728
    cudaFuncSetAttribute(k_simgemm_sym,
                         cudaFuncAttributeMaxDynamicSharedMemorySize, smem_bytes);

    k_normalize<<<Nn / 16, 256>>>(zi, zj, B);
    const int ntiles = Nn / TILE;                  // 64
    const int NT = ntiles * (ntiles + 1) / 2;      // 2080
    k_simgemm_sym<<<NT, 256, smem_bytes>>>(Nn, B, NT, (float*)d_out);
}

// round 17
// speedup vs baseline: 1.1829x; 1.1829x over previous
#include <cuda_runtime.h>
#include <cstdint>
#include <math.h>

#define D 256
#define MAXN 8192
#define TILE 128
#define CHKB 144                     // smem row bytes: 144 = 9*16 (cp.async-aligned);
                                     // 36 words == 4 mod 32 -> conflict-free ldmatrix
#define ST_BYTES (TILE * CHKB)       // one stage = 18432 B (K-chunk of 128 s8)

// Scratch (__device__ globals: allocation-free rule)
__device__ int8_t g_znq[MAXN * D];   // normalized rows, s8 (scale 127), 2 MB
__device__ float g_S[MAXN];          // sum_{j!=i} exp(sim_ij - 2)
__device__ float g_pos[MAXN];        // sim[i, partner(i)]

__device__ __forceinline__ uint32_t smem_u32(const void* p) {
    uint32_t a;
    asm("{ .reg .u64 t; cvta.to.shared.u64 t, %1; cvt.u32.u64 %0, t; }"
        : "=r"(a) : "l"(p));
    return a;
}
__device__ __forceinline__ void cp_async16(uint32_t dst, const void* src) {
    asm volatile("cp.async.cg.shared.global [%0], [%1], 16;" :: "r"(dst), "l"(src));
}
#define CP_COMMIT() asm volatile("cp.async.commit_group;" ::: "memory")
#define CP_WAIT(n)  asm volatile("cp.async.wait_group %0;" :: "n"(n) : "memory")

// ---------------------------------------------------------------------------
// exp(sim-2) from the s32 accumulator via the MUFU pipe:
//   exp(sim-2) = 2^(a*C1 + C0);  1 cvt + 1 FMA + 1 ex2.approx per element.
// ---------------------------------------------------------------------------
#define EXP_C1 (1.7886898e-4f)        // 2 * log2(e) / 16129
#define EXP_C0 (-2.8853900817779268f) // -2 * log2(e)
__device__ __forceinline__ float exp2_mufu(float t) {
    float r;
    asm("ex2.approx.f32 %0, %1;" : "=f"(r) : "f"(t));
    return r;
}

// ---------------------------------------------------------------------------
// Kernel 1: normalize rows -> s8 (scale 127). Warp handles 2 rows (MLP x2);
// 16 rows/block, grid 512.
// ---------------------------------------------------------------------------
__global__ __launch_bounds__(256)
void k_normalize(const float* __restrict__ zi,
                 const float* __restrict__ zj, int B) {
    const int w   = threadIdx.x >> 5;
    const int lid = threadIdx.x & 31;
    const int row0 = blockIdx.x * 16 + w * 2;

    const float* srcA = (row0 < B) ? (zi + (size_t)row0 * D)
                                   : (zj + (size_t)(row0 - B) * D);
    const int row1 = row0 + 1;
    const float* srcB = (row1 < B) ? (zi + (size_t)row1 * D)
                                   : (zj + (size_t)(row1 - B) * D);

    float4 a0 = *reinterpret_cast<const float4*>(srcA + lid * 8);
    float4 a1 = *reinterpret_cast<const float4*>(srcA + lid * 8 + 4);
    float4 b0 = *reinterpret_cast<const float4*>(srcB + lid * 8);
    float4 b1 = *reinterpret_cast<const float4*>(srcB + lid * 8 + 4);

    float sa = a0.x*a0.x + a0.y*a0.y + a0.z*a0.z + a0.w*a0.w
             + a1.x*a1.x + a1.y*a1.y + a1.z*a1.z + a1.w*a1.w;
    float sb = b0.x*b0.x + b0.y*b0.y + b0.z*b0.z + b0.w*b0.w
             + b1.x*b1.x + b1.y*b1.y + b1.z*b1.z + b1.w*b1.w;
    #pragma unroll
    for (int o = 16; o > 0; o >>= 1) {
        sa += __shfl_xor_sync(0xffffffffu, sa, o);
        sb += __shfl_xor_sync(0xffffffffu, sb, o);
    }
    float qa = 127.0f / fmaxf(sqrtf(sa), 1e-8f);
    float qb = 127.0f / fmaxf(sqrtf(sb), 1e-8f);

    auto pack8 = [](float4 v0, float4 v1, float q, uint2& pk) {
        int i0 = __float2int_rn(v0.x * q), i1 = __float2int_rn(v0.y * q);
        int i2 = __float2int_rn(v0.z * q), i3 = __float2int_rn(v0.w * q);
        int i4 = __float2int_rn(v1.x * q), i5 = __float2int_rn(v1.y * q);
        int i6 = __float2int_rn(v1.z * q), i7 = __float2int_rn(v1.w * q);
        pk.x = (uint32_t)(i0 & 255) | ((uint32_t)(i1 & 255) << 8) |
               ((uint32_t)(i2 & 255) << 16) | ((uint32_t)(i3 & 255) << 24);
        pk.y = (uint32_t)(i4 & 255) | ((uint32_t)(i5 & 255) << 8) |
               ((uint32_t)(i6 & 255) << 16) | ((uint32_t)(i7 & 255) << 24);
    };
    uint2 pa, pb;
    pack8(a0, a1, qa, pa);
    pack8(b0, b1, qb, pb);
    *reinterpret_cast<uint2*>(&g_znq[(size_t)row0 * D + lid * 8]) = pa;
    *reinterpret_cast<uint2*>(&g_znq[(size_t)row1 * D + lid * 8]) = pb;
    if (lid == 0) {
        g_S[row0] = 0.0f; g_pos[row0] = 0.0f;
        g_S[row1] = 0.0f; g_pos[row1] = 0.0f;
    }
}

// ---------------------------------------------------------------------------
// Kernel 2: lower-triangle 128x128 tiles (2080 CTAs), s8 mma.sync.m16n8k32,
// MUFU exp epilogue specialized per tile class:
//   plain (1984): no compares at all, row+col sums
//   diag   (64) : row sums only, c==r mask
//   pos    (32) : full path with partner capture
// No fused final reduction (R16's per-CTA __threadfence regressed 10us).
// ---------------------------------------------------------------------------
__global__ __launch_bounds__(256, 2)
void k_simgemm_sym(int Nn, int B) {
    extern __shared__ uint8_t smem[];
    uint8_t* As = smem;                      // 2 stages
    uint8_t* Bs = smem + 2 * ST_BYTES;       // 2 stages

    // decode lower-triangle tile (by >= bx)
    int idx = blockIdx.x;
    int by = (int)((sqrtf(8.0f * (float)idx + 1.0f) - 1.0f) * 0.5f);
    while ((by + 1) * (by + 2) / 2 <= idx) by++;
    while (by * (by + 1) / 2 > idx) by--;
    int bx = idx - by * (by + 1) / 2;
    const int r0 = by * TILE, c0 = bx * TILE;
    const bool diag = (by == bx);
    const bool has_pos = (by == bx + (B / TILE));

    const int tid = threadIdx.x;
    const int wid = tid >> 5, lid = tid & 31;

    auto issue_chunk = [&](int ch) {
        #pragma unroll
        for (int q = 0; q < 4; q++) {
            int li  = tid + q * 256;            // 0..1023
            int row = li >> 3;                  // 0..127
            int seg = (li & 7) << 4;            // 0..112 bytes
            uint32_t dstA = smem_u32(&As[ch * ST_BYTES + row * CHKB + seg]);
            uint32_t dstB = smem_u32(&Bs[ch * ST_BYTES + row * CHKB + seg]);
            cp_async16(dstA, &g_znq[(size_t)(r0 + row) * D + ch * 128 + seg]);
            cp_async16(dstB, &g_znq[(size_t)(c0 + row) * D + ch * 128 + seg]);
        }
        CP_COMMIT();
    };

    issue_chunk(0);
    issue_chunk(1);

    const int warp_m = wid & 3;
    const int warp_n = wid >> 2;

    uint32_t aAddr[2];
    #pragma unroll
    for (int mf = 0; mf < 2; mf++) {
        int row  = warp_m * 32 + mf * 16 + (lid & 15);
        int colb = (lid >> 4) << 4;
        aAddr[mf] = smem_u32(&As[row * CHKB + colb]);
    }
    uint32_t bAddr[4];
    #pragma unroll
    for (int nq = 0; nq < 4; nq++) {
        int row  = warp_n * 64 + nq * 16 + ((lid >> 4) << 3) + (lid & 7);
        int colb = (lid & 8) << 1;
        bAddr[nq] = smem_u32(&Bs[row * CHKB + colb]);
    }

    int acc[2][8][4];
    #pragma unroll
    for (int i = 0; i < 2; i++)
        #pragma unroll
        for (int j = 0; j < 8; j++)
            #pragma unroll
            for (int e = 0; e < 4; e++) acc[i][j][e] = 0;

    #pragma unroll
    for (int ch = 0; ch < 2; ch++) {
        if (ch == 0) CP_WAIT(1); else CP_WAIT(0);
        __syncthreads();
        const uint32_t cb = (uint32_t)ch * ST_BYTES;
        #pragma unroll
        for (int ks = 0; ks < 4; ks++) {
            const uint32_t kb = cb + ks * 32;
            uint32_t a[2][4], b[4][4];
            #pragma unroll
            for (int mf = 0; mf < 2; mf++)
                asm volatile("ldmatrix.sync.aligned.m8n8.x4.shared.b16 {%0,%1,%2,%3}, [%4];"
                             : "=r"(a[mf][0]), "=r"(a[mf][1]), "=r"(a[mf][2]), "=r"(a[mf][3])
                             : "r"(aAddr[mf] + kb));
            #pragma unroll
            for (int nq = 0; nq < 4; nq++)
                asm volatile("ldmatrix.sync.aligned.m8n8.x4.shared.b16 {%0,%1,%2,%3}, [%4];"
                             : "=r"(b[nq][0]), "=r"(b[nq][1]), "=r"(b[nq][2]), "=r"(b[nq][3])
                             : "r"(bAddr[nq] + kb));
            #pragma unroll
            for (int mf = 0; mf < 2; mf++)
                #pragma unroll
                for (int nf = 0; nf < 8; nf++) {
                    const int nq = nf >> 1, base = (nf & 1) * 2;
                    asm volatile(
                        "mma.sync.aligned.m16n8k32.row.col.s32.s8.s8.s32 "
                        "{%0,%1,%2,%3}, {%4,%5,%6,%7}, {%8,%9}, {%0,%1,%2,%3};"
                        : "+r"(acc[mf][nf][0]), "+r"(acc[mf][nf][1]),
                          "+r"(acc[mf][nf][2]), "+r"(acc[mf][nf][3])
                        : "r"(a[mf][0]), "r"(a[mf][1]), "r"(a[mf][2]), "r"(a[mf][3]),
                          "r"(b[nq][base]), "r"(b[nq][base + 1]));
                }
        }
    }

    // ---------------------- specialized epilogues --------------------------
    const float SC = 2.0f / 16129.0f;
    const int qrow = lid >> 2, qcol = lid & 3;
    float rs[4] = {0.f, 0.f, 0.f, 0.f};
    float cs[8][2];
    #pragma unroll
    for (int nf = 0; nf < 8; nf++) { cs[nf][0] = 0.f; cs[nf][1] = 0.f; }

    if (!diag && !has_pos) {
        // plain tile: no index math, no compares — pure exp + dual sums
        #pragma unroll
        for (int mf = 0; mf < 2; mf++)
            #pragma unroll
            for (int sub = 0; sub < 2; sub++)
                #pragma unroll
                for (int nf = 0; nf < 8; nf++)
                    #pragma unroll
                    for (int e = 0; e < 2; e++) {
                        float ex = exp2_mufu(
                            fmaf((float)acc[mf][nf][sub * 2 + e], EXP_C1, EXP_C0));
                        rs[mf * 2 + sub] += ex;
                        cs[nf][e] += ex;
                    }
    } else if (diag) {
        // diagonal tile: row sums only (mirror is self), mask c == r
        #pragma unroll
        for (int mf = 0; mf < 2; mf++)
            #pragma unroll
            for (int sub = 0; sub < 2; sub++) {
                const int rloc = warp_m * 32 + mf * 16 + sub * 8 + qrow;
                #pragma unroll
                for (int nf = 0; nf < 8; nf++)
                    #pragma unroll
                    for (int e = 0; e < 2; e++) {
                        const int cloc = warp_n * 64 + nf * 8 + qcol * 2 + e;
                        float ex = exp2_mufu(
                            fmaf((float)acc[mf][nf][sub * 2 + e], EXP_C1, EXP_C0));
                        if (cloc == rloc) ex = 0.0f;
                        rs[mf * 2 + sub] += ex;
                    }
            }
    } else {
        // pos tile (by == bx + B/TILE): full path with partner capture
        #pragma unroll
        for (int mf = 0; mf < 2; mf++)
            #pragma unroll
            for (int sub = 0; sub < 2; sub++) {
                const int r = r0 + warp_m * 32 + mf * 16 + sub * 8 + qrow;
                const int partner = r - B;   // r >= B on these tiles
                #pragma unroll
                for (int nf = 0; nf < 8; nf++)
                    #pragma unroll
                    for (int e = 0; e < 2; e++) {
                        const int c = c0 + warp_n * 64 + nf * 8 + qcol * 2 + e;
                        const int av = acc[mf][nf][sub * 2 + e];
                        float ex = exp2_mufu(fmaf((float)av, EXP_C1, EXP_C0));
                        rs[mf * 2 + sub] += ex;
                        cs[nf][e] += ex;
                        if (c == partner) {
                            const float sim = SC * (float)av;
                            g_pos[r] = sim; g_pos[c] = sim;
                        }
                    }
            }
    }

    // row sums: reduce across qcol (lanes 1,2)
    #pragma unroll
    for (int i = 0; i < 4; i++) {
        rs[i] += __shfl_xor_sync(0xffffffffu, rs[i], 1);
        rs[i] += __shfl_xor_sync(0xffffffffu, rs[i], 2);
    }
    if (qcol == 0) {
        #pragma unroll
        for (int mf = 0; mf < 2; mf++)
            #pragma unroll
            for (int sub = 0; sub < 2; sub++) {
                const int r = r0 + warp_m * 32 + mf * 16 + sub * 8 + qrow;
                atomicAdd(&g_S[r], rs[mf * 2 + sub]);
            }
    }

    // col sums: reduce across qrow (lanes 4,8,16); lanes 0..3 write
    if (!diag) {
        #pragma unroll
        for (int nf = 0; nf < 8; nf++) {
            #pragma unroll
            for (int e = 0; e < 2; e++) {
                float v = cs[nf][e];
                v += __shfl_xor_sync(0xffffffffu, v, 4);
                v += __shfl_xor_sync(0xffffffffu, v, 8);
                v += __shfl_xor_sync(0xffffffffu, v, 16);
                if (lid < 4) {
                    const int c = c0 + warp_n * 64 + nf * 8 + qcol * 2 + e;
                    atomicAdd(&g_S[c], v);
                }
            }
        }
    }
}

// ---------------------------------------------------------------------------
// Kernel 3: loss = (1/N) * sum_i (2 + log(S_i) - pos_i)
// ---------------------------------------------------------------------------
__global__ void k_final(float* __restrict__ out, int Nn) {
    int t = threadIdx.x;
    float s = 0.0f;
    for (int i = t; i < Nn; i += 1024)
        s += 2.0f + logf(g_S[i]) - g_pos[i];
    #pragma unroll
    for (int o = 16; o > 0; o >>= 1) s += __shfl_xor_sync(0xffffffffu, s, o);
    __shared__ float ws[32];
    if ((t & 31) == 0) ws[t >> 5] = s;
    __syncthreads();
    if (t < 32) {
        float x = ws[t];
        #pragma unroll
        for (int o = 16; o > 0; o >>= 1) x += __shfl_xor_sync(0xffffffffu, x, o);
        if (t == 0) out[0] = x / (float)Nn;
    }
}

// ---------------------------------------------------------------------------
extern "C" void kernel_launch(void* const* d_in, const int* in_sizes, int n_in,
                              void* d_out, int out_size) {
    const float* zi = (const float*)d_in[0];
    const float* zj = (const float*)d_in[1];
    int B  = in_sizes[0] / D;   // 4096
    int Nn = 2 * B;             // 8192

    const int smem_bytes = 4 * ST_BYTES;   // 73728
    cudaFuncSetAttribute(k_simgemm_sym,
                         cudaFuncAttributeMaxDynamicSharedMemorySize, smem_bytes);

    k_normalize<<<Nn / 16, 256>>>(zi, zj, B);
    const int ntiles = Nn / TILE;                  // 64
    const int nblocks = ntiles * (ntiles + 1) / 2; // 2080
    k_simgemm_sym<<<nblocks, 256, smem_bytes>>>(Nn, B);
    k_final<<<1, 1024>>>((float*)d_out, Nn);
}